// round 10
// baseline (speedup 1.0000x reference)
#include <cuda_runtime.h>
#include <cstdint>

// Causal attention: out = softmax(QK^T / sqrt(64) + causal) V
// B=4, H=16, S=2048, Dh=64, fp32. FA-2 style, tf32 mma.sync, sm_103a.
//
// R9 changes vs R8 (263us, tensor=44.5%, phase-serialized at 1 CTA/SM):
//  - 128 threads/CTA (4 warps x 32 rows, BM=128), Q smem eliminated (fragments
//    loaded once from global) -> smem 71.7KB/CTA, regs 128x256x2 = full RF
//    -> 2 independent CTAs/SM. Each SMSP now carries one warp from each CTA:
//    one CTA's tensor phase overlaps the other's softmax phase.
//  - QK loop interchanged (kk outer, n inner): 16 independent accumulator
//    chains instead of 2 -> better tensor ILP within a phase.

#define S_LEN   2048
#define DH      64
#define BM      128
#define BN      64
#define KSK     68
#define KSV     72
#define NEG_INF __int_as_float(0xff800000)

__device__ __forceinline__ uint32_t f2tf(float x) {
    uint32_t y;
    asm("cvt.rna.tf32.f32 %0, %1;" : "=r"(y) : "f"(x));
    return y;
}

__device__ __forceinline__ float fexp2(float x) {
    float y;
    asm("ex2.approx.ftz.f32 %0, %1;" : "=f"(y) : "f"(x));
    return y;
}

__device__ __forceinline__ void cp16(float* dst, const float* src) {
    uint32_t d = (uint32_t)__cvta_generic_to_shared(dst);
    asm volatile("cp.async.cg.shared.global [%0], [%1], 16;" :: "r"(d), "l"(src));
}

__device__ __forceinline__ void mma_tf32(float c[4], const uint32_t a[4],
                                         uint32_t b0, uint32_t b1) {
    asm volatile(
        "mma.sync.aligned.m16n8k8.row.col.f32.tf32.tf32.f32 "
        "{%0,%1,%2,%3}, {%4,%5,%6,%7}, {%8,%9}, {%0,%1,%2,%3};"
        : "+f"(c[0]), "+f"(c[1]), "+f"(c[2]), "+f"(c[3])
        : "r"(a[0]), "r"(a[1]), "r"(a[2]), "r"(a[3]), "r"(b0), "r"(b1));
}

// V rows permuted within each octet so the QK C-fragment IS the PV A-fragment.
__device__ __forceinline__ int vperm(int r) {
    return (r & ~7) | (((r & 1) << 2) | ((r & 7) >> 1));
}

// 128 threads load a 64x64 fp32 tile pair (K and V) via cp.async.
__device__ __forceinline__ void load_kv_tile(float* kd, float* vd,
                                             const float* ksrc, const float* vsrc,
                                             int t) {
    int r = t >> 4;                 // 0..7
    int c = (t & 15) << 2;          // 0..60 step 4
    #pragma unroll
    for (int i = 0; i < 8; i++) {
        int row = r + 8 * i;
        cp16(kd + row * KSK + c, ksrc + row * DH + c);
        cp16(vd + vperm(row) * KSV + c, vsrc + row * DH + c);
    }
}

__global__ __launch_bounds__(128, 2)
void fa_kernel(const float* __restrict__ q, const float* __restrict__ k,
               const float* __restrict__ v, float* __restrict__ o)
{
    extern __shared__ float sm[];
    float* ks0 = sm;                         // 2 * BN * KSK
    float* vs0 = sm + 2 * BN * KSK;          // 2 * BN * KSV

    const int t    = threadIdx.x;
    const int lane = t & 31;
    const int w    = t >> 5;                 // warp 0..3 -> rows [32w, 32w+32)
    const int g    = lane & 3;
    const int qr   = lane >> 2;

    const int bx   = (gridDim.x - 1) - blockIdx.x;   // heavy CTAs first
    const int head = blockIdx.y;
    const size_t base = (size_t)head * (S_LEN * DH);

    const float* qg = q + base + (size_t)bx * BM * DH;
    const float* kg = k + base;
    const float* vg = v + base;

    const int ntiles = 2 * bx + 2;

    load_kv_tile(ks0, vs0, kg, vg, t);
    asm volatile("cp.async.commit_group;");

    // ---- Q A-fragments straight from global (one-time), scaled, tf32 ----
    const float SC = 0.18033688011112042f;    // log2(e)/8
    uint32_t qa[2][8][4];
    #pragma unroll
    for (int rb = 0; rb < 2; rb++) {
        const float* q0 = qg + (size_t)(w * 32 + rb * 16 + qr) * DH;
        const float* q1 = q0 + 8 * DH;
        #pragma unroll
        for (int kk = 0; kk < 8; kk++) {
            qa[rb][kk][0] = f2tf(__ldg(q0 + 8 * kk + g    ) * SC);
            qa[rb][kk][1] = f2tf(__ldg(q1 + 8 * kk + g    ) * SC);
            qa[rb][kk][2] = f2tf(__ldg(q0 + 8 * kk + g + 4) * SC);
            qa[rb][kk][3] = f2tf(__ldg(q1 + 8 * kk + g + 4) * SC);
        }
    }

    float oc[2][8][4];
    #pragma unroll
    for (int rb = 0; rb < 2; rb++)
        #pragma unroll
        for (int d = 0; d < 8; d++)
            oc[rb][d][0] = oc[rb][d][1] = oc[rb][d][2] = oc[rb][d][3] = 0.f;

    float m[2][2], l[2][2];
    #pragma unroll
    for (int rb = 0; rb < 2; rb++) { m[rb][0] = m[rb][1] = NEG_INF; l[rb][0] = l[rb][1] = 0.f; }

    int rg[2][2];
    #pragma unroll
    for (int rb = 0; rb < 2; rb++) {
        rg[rb][0] = bx * BM + w * 32 + 16 * rb + qr;
        rg[rb][1] = rg[rb][0] + 8;
    }

    for (int j = 0; j < ntiles; j++) {
        float* ksb = ks0 + (j & 1) * BN * KSK;
        float* vsb = vs0 + (j & 1) * BN * KSV;

        if (j + 1 < ntiles) {
            load_kv_tile(ks0 + ((j + 1) & 1) * BN * KSK,
                         vs0 + ((j + 1) & 1) * BN * KSV,
                         kg + (size_t)(j + 1) * BN * DH,
                         vg + (size_t)(j + 1) * BN * DH, t);
            asm volatile("cp.async.commit_group;");
            asm volatile("cp.async.wait_group 1;");
        } else {
            asm volatile("cp.async.wait_group 0;");
        }
        __syncthreads();

        const bool active = (64 * j <= bx * BM + w * 32 + 31);
        if (active) {
            float sc[2][8][4];
            #pragma unroll
            for (int rb = 0; rb < 2; rb++)
                #pragma unroll
                for (int n = 0; n < 8; n++)
                    sc[rb][n][0] = sc[rb][n][1] = sc[rb][n][2] = sc[rb][n][3] = 0.f;

            // ---- S = Q K^T : kk outer -> 16 independent accumulator chains
            #pragma unroll
            for (int kk = 0; kk < 8; kk++) {
                const float* kb = ksb + qr * KSK + 8 * kk + g;
                #pragma unroll
                for (int n = 0; n < 8; n++) {
                    uint32_t b0 = __float_as_uint(kb[(8 * n) * KSK    ]);
                    uint32_t b1 = __float_as_uint(kb[(8 * n) * KSK + 4]);
                    mma_tf32(sc[0][n], qa[0][kk], b0, b1);
                    mma_tf32(sc[1][n], qa[1][kk], b0, b1);
                }
            }

            // ---- causal mask ----
            #pragma unroll
            for (int rb = 0; rb < 2; rb++) {
                if (64 * j + 63 > rg[rb][0]) {
                    #pragma unroll
                    for (int n = 0; n < 8; n++) {
                        int c0 = 64 * j + 8 * n + 2 * g;
                        if (c0     > rg[rb][0]) sc[rb][n][0] = NEG_INF;
                        if (c0 + 1 > rg[rb][0]) sc[rb][n][1] = NEG_INF;
                    }
                }
                if (64 * j + 63 > rg[rb][1]) {
                    #pragma unroll
                    for (int n = 0; n < 8; n++) {
                        int c0 = 64 * j + 8 * n + 2 * g;
                        if (c0     > rg[rb][1]) sc[rb][n][2] = NEG_INF;
                        if (c0 + 1 > rg[rb][1]) sc[rb][n][3] = NEG_INF;
                    }
                }
            }

            // ---- online softmax (base-2) ----
            #pragma unroll
            for (int rb = 0; rb < 2; rb++) {
                float tm0 = NEG_INF, tm1 = NEG_INF;
                #pragma unroll
                for (int n = 0; n < 8; n++) {
                    tm0 = fmaxf(tm0, fmaxf(sc[rb][n][0], sc[rb][n][1]));
                    tm1 = fmaxf(tm1, fmaxf(sc[rb][n][2], sc[rb][n][3]));
                }
                tm0 = fmaxf(tm0, __shfl_xor_sync(0xffffffffu, tm0, 1));
                tm0 = fmaxf(tm0, __shfl_xor_sync(0xffffffffu, tm0, 2));
                tm1 = fmaxf(tm1, __shfl_xor_sync(0xffffffffu, tm1, 1));
                tm1 = fmaxf(tm1, __shfl_xor_sync(0xffffffffu, tm1, 2));

                float mn0 = fmaxf(m[rb][0], tm0), mn1 = fmaxf(m[rb][1], tm1);
                float f0 = fexp2(m[rb][0] - mn0);
                float f1 = fexp2(m[rb][1] - mn1);
                m[rb][0] = mn0; m[rb][1] = mn1;
                l[rb][0] *= f0; l[rb][1] *= f1;
                #pragma unroll
                for (int d = 0; d < 8; d++) {
                    oc[rb][d][0] *= f0; oc[rb][d][1] *= f0;
                    oc[rb][d][2] *= f1; oc[rb][d][3] *= f1;
                }
                #pragma unroll
                for (int n = 0; n < 8; n++) {
                    float p0 = fexp2(sc[rb][n][0] - mn0);
                    float p1 = fexp2(sc[rb][n][1] - mn0);
                    float p2 = fexp2(sc[rb][n][2] - mn1);
                    float p3 = fexp2(sc[rb][n][3] - mn1);
                    l[rb][0] += p0 + p1;
                    l[rb][1] += p2 + p3;
                    sc[rb][n][0] = __uint_as_float(f2tf(p0));
                    sc[rb][n][1] = __uint_as_float(f2tf(p1));
                    sc[rb][n][2] = __uint_as_float(f2tf(p2));
                    sc[rb][n][3] = __uint_as_float(f2tf(p3));
                }
            }

            // ---- O += P V : C-frag == A-frag under V row permutation ----
            #pragma unroll
            for (int kt = 0; kt < 8; kt++) {
                uint32_t pa0[4], pa1[4];
                pa0[0] = __float_as_uint(sc[0][kt][0]);
                pa0[1] = __float_as_uint(sc[0][kt][2]);
                pa0[2] = __float_as_uint(sc[0][kt][1]);
                pa0[3] = __float_as_uint(sc[0][kt][3]);
                pa1[0] = __float_as_uint(sc[1][kt][0]);
                pa1[1] = __float_as_uint(sc[1][kt][2]);
                pa1[2] = __float_as_uint(sc[1][kt][1]);
                pa1[3] = __float_as_uint(sc[1][kt][3]);

                const float* vb = vsb + (8 * kt + g) * KSV + qr;
                #pragma unroll
                for (int d = 0; d < 8; d++) {
                    uint32_t b0 = __float_as_uint(vb[8 * d]);
                    uint32_t b1 = __float_as_uint(vb[4 * KSV + 8 * d]);
                    mma_tf32(oc[0][d], pa0, b0, b1);
                    mma_tf32(oc[1][d], pa1, b0, b1);
                }
            }
        }
        __syncthreads();
    }

    // ---- finalize ----
    #pragma unroll
    for (int rb = 0; rb < 2; rb++) {
        float l0 = l[rb][0], l1 = l[rb][1];
        l0 += __shfl_xor_sync(0xffffffffu, l0, 1);
        l0 += __shfl_xor_sync(0xffffffffu, l0, 2);
        l1 += __shfl_xor_sync(0xffffffffu, l1, 1);
        l1 += __shfl_xor_sync(0xffffffffu, l1, 2);
        float inv0 = 1.0f / l0, inv1 = 1.0f / l1;

        float* o0 = o + base + (size_t)rg[rb][0] * DH;
        float* o1 = o + base + (size_t)rg[rb][1] * DH;
        #pragma unroll
        for (int d = 0; d < 8; d++) {
            float2 a, b;
            a.x = oc[rb][d][0] * inv0; a.y = oc[rb][d][1] * inv0;
            b.x = oc[rb][d][2] * inv1; b.y = oc[rb][d][3] * inv1;
            *(float2*)(o0 + 8 * d + 2 * g) = a;
            *(float2*)(o1 + 8 * d + 2 * g) = b;
        }
    }
}

extern "C" void kernel_launch(void* const* d_in, const int* in_sizes, int n_in,
                              void* d_out, int out_size)
{
    const float* q = (const float*)d_in[0];
    const float* k = (const float*)d_in[1];
    const float* v = (const float*)d_in[2];
    // d_in[3] (causal mask) applied analytically; not read.
    float* o = (float*)d_out;

    const int heads = in_sizes[0] / (S_LEN * DH);      // 64
    const int SMEM  = (2 * BN * KSK + 2 * BN * KSV) * (int)sizeof(float);  // 71680

    cudaFuncSetAttribute(fa_kernel, cudaFuncAttributeMaxDynamicSharedMemorySize, SMEM);

    dim3 grid(S_LEN / BM, heads);   // (16, 64)
    fa_kernel<<<grid, 128, SMEM>>>(q, k, v, o);
}

// round 11
// speedup vs baseline: 1.0005x; 1.0005x over previous
#include <cuda_runtime.h>
#include <cstdint>

// Causal attention: out = softmax(QK^T / sqrt(64) + causal) V
// B=4, H=16, S=2048, Dh=64, fp32. FA-2 style, tf32 mma.sync, sm_103a.
//
// R9 changes vs R8 (263us, tensor=44.5%, phase-serialized at 1 CTA/SM):
//  - 128 threads/CTA (4 warps x 32 rows, BM=128), Q smem eliminated (fragments
//    loaded once from global) -> smem 71.7KB/CTA, regs 128x256x2 = full RF
//    -> 2 independent CTAs/SM. Each SMSP now carries one warp from each CTA:
//    one CTA's tensor phase overlaps the other's softmax phase.
//  - QK loop interchanged (kk outer, n inner): 16 independent accumulator
//    chains instead of 2 -> better tensor ILP within a phase.

#define S_LEN   2048
#define DH      64
#define BM      128
#define BN      64
#define KSK     68
#define KSV     72
#define NEG_INF __int_as_float(0xff800000)

__device__ __forceinline__ uint32_t f2tf(float x) {
    uint32_t y;
    asm("cvt.rna.tf32.f32 %0, %1;" : "=r"(y) : "f"(x));
    return y;
}

__device__ __forceinline__ float fexp2(float x) {
    float y;
    asm("ex2.approx.ftz.f32 %0, %1;" : "=f"(y) : "f"(x));
    return y;
}

__device__ __forceinline__ void cp16(float* dst, const float* src) {
    uint32_t d = (uint32_t)__cvta_generic_to_shared(dst);
    asm volatile("cp.async.cg.shared.global [%0], [%1], 16;" :: "r"(d), "l"(src));
}

__device__ __forceinline__ void mma_tf32(float c[4], const uint32_t a[4],
                                         uint32_t b0, uint32_t b1) {
    asm volatile(
        "mma.sync.aligned.m16n8k8.row.col.f32.tf32.tf32.f32 "
        "{%0,%1,%2,%3}, {%4,%5,%6,%7}, {%8,%9}, {%0,%1,%2,%3};"
        : "+f"(c[0]), "+f"(c[1]), "+f"(c[2]), "+f"(c[3])
        : "r"(a[0]), "r"(a[1]), "r"(a[2]), "r"(a[3]), "r"(b0), "r"(b1));
}

// V rows permuted within each octet so the QK C-fragment IS the PV A-fragment.
__device__ __forceinline__ int vperm(int r) {
    return (r & ~7) | (((r & 1) << 2) | ((r & 7) >> 1));
}

// 128 threads load a 64x64 fp32 tile pair (K and V) via cp.async.
__device__ __forceinline__ void load_kv_tile(float* kd, float* vd,
                                             const float* ksrc, const float* vsrc,
                                             int t) {
    int r = t >> 4;                 // 0..7
    int c = (t & 15) << 2;          // 0..60 step 4
    #pragma unroll
    for (int i = 0; i < 8; i++) {
        int row = r + 8 * i;
        cp16(kd + row * KSK + c, ksrc + row * DH + c);
        cp16(vd + vperm(row) * KSV + c, vsrc + row * DH + c);
    }
}

__global__ __launch_bounds__(128, 2)
void fa_kernel(const float* __restrict__ q, const float* __restrict__ k,
               const float* __restrict__ v, float* __restrict__ o)
{
    extern __shared__ float sm[];
    float* ks0 = sm;                         // 2 * BN * KSK
    float* vs0 = sm + 2 * BN * KSK;          // 2 * BN * KSV

    const int t    = threadIdx.x;
    const int lane = t & 31;
    const int w    = t >> 5;                 // warp 0..3 -> rows [32w, 32w+32)
    const int g    = lane & 3;
    const int qr   = lane >> 2;

    const int bx   = (gridDim.x - 1) - blockIdx.x;   // heavy CTAs first
    const int head = blockIdx.y;
    const size_t base = (size_t)head * (S_LEN * DH);

    const float* qg = q + base + (size_t)bx * BM * DH;
    const float* kg = k + base;
    const float* vg = v + base;

    const int ntiles = 2 * bx + 2;

    load_kv_tile(ks0, vs0, kg, vg, t);
    asm volatile("cp.async.commit_group;");

    // ---- Q A-fragments straight from global (one-time), scaled, tf32 ----
    const float SC = 0.18033688011112042f;    // log2(e)/8
    uint32_t qa[2][8][4];
    #pragma unroll
    for (int rb = 0; rb < 2; rb++) {
        const float* q0 = qg + (size_t)(w * 32 + rb * 16 + qr) * DH;
        const float* q1 = q0 + 8 * DH;
        #pragma unroll
        for (int kk = 0; kk < 8; kk++) {
            qa[rb][kk][0] = f2tf(__ldg(q0 + 8 * kk + g    ) * SC);
            qa[rb][kk][1] = f2tf(__ldg(q1 + 8 * kk + g    ) * SC);
            qa[rb][kk][2] = f2tf(__ldg(q0 + 8 * kk + g + 4) * SC);
            qa[rb][kk][3] = f2tf(__ldg(q1 + 8 * kk + g + 4) * SC);
        }
    }

    float oc[2][8][4];
    #pragma unroll
    for (int rb = 0; rb < 2; rb++)
        #pragma unroll
        for (int d = 0; d < 8; d++)
            oc[rb][d][0] = oc[rb][d][1] = oc[rb][d][2] = oc[rb][d][3] = 0.f;

    float m[2][2], l[2][2];
    #pragma unroll
    for (int rb = 0; rb < 2; rb++) { m[rb][0] = m[rb][1] = NEG_INF; l[rb][0] = l[rb][1] = 0.f; }

    int rg[2][2];
    #pragma unroll
    for (int rb = 0; rb < 2; rb++) {
        rg[rb][0] = bx * BM + w * 32 + 16 * rb + qr;
        rg[rb][1] = rg[rb][0] + 8;
    }

    for (int j = 0; j < ntiles; j++) {
        float* ksb = ks0 + (j & 1) * BN * KSK;
        float* vsb = vs0 + (j & 1) * BN * KSV;

        if (j + 1 < ntiles) {
            load_kv_tile(ks0 + ((j + 1) & 1) * BN * KSK,
                         vs0 + ((j + 1) & 1) * BN * KSV,
                         kg + (size_t)(j + 1) * BN * DH,
                         vg + (size_t)(j + 1) * BN * DH, t);
            asm volatile("cp.async.commit_group;");
            asm volatile("cp.async.wait_group 1;");
        } else {
            asm volatile("cp.async.wait_group 0;");
        }
        __syncthreads();

        const bool active = (64 * j <= bx * BM + w * 32 + 31);
        if (active) {
            float sc[2][8][4];
            #pragma unroll
            for (int rb = 0; rb < 2; rb++)
                #pragma unroll
                for (int n = 0; n < 8; n++)
                    sc[rb][n][0] = sc[rb][n][1] = sc[rb][n][2] = sc[rb][n][3] = 0.f;

            // ---- S = Q K^T : kk outer -> 16 independent accumulator chains
            #pragma unroll
            for (int kk = 0; kk < 8; kk++) {
                const float* kb = ksb + qr * KSK + 8 * kk + g;
                #pragma unroll
                for (int n = 0; n < 8; n++) {
                    uint32_t b0 = __float_as_uint(kb[(8 * n) * KSK    ]);
                    uint32_t b1 = __float_as_uint(kb[(8 * n) * KSK + 4]);
                    mma_tf32(sc[0][n], qa[0][kk], b0, b1);
                    mma_tf32(sc[1][n], qa[1][kk], b0, b1);
                }
            }

            // ---- causal mask ----
            #pragma unroll
            for (int rb = 0; rb < 2; rb++) {
                if (64 * j + 63 > rg[rb][0]) {
                    #pragma unroll
                    for (int n = 0; n < 8; n++) {
                        int c0 = 64 * j + 8 * n + 2 * g;
                        if (c0     > rg[rb][0]) sc[rb][n][0] = NEG_INF;
                        if (c0 + 1 > rg[rb][0]) sc[rb][n][1] = NEG_INF;
                    }
                }
                if (64 * j + 63 > rg[rb][1]) {
                    #pragma unroll
                    for (int n = 0; n < 8; n++) {
                        int c0 = 64 * j + 8 * n + 2 * g;
                        if (c0     > rg[rb][1]) sc[rb][n][2] = NEG_INF;
                        if (c0 + 1 > rg[rb][1]) sc[rb][n][3] = NEG_INF;
                    }
                }
            }

            // ---- online softmax (base-2) ----
            #pragma unroll
            for (int rb = 0; rb < 2; rb++) {
                float tm0 = NEG_INF, tm1 = NEG_INF;
                #pragma unroll
                for (int n = 0; n < 8; n++) {
                    tm0 = fmaxf(tm0, fmaxf(sc[rb][n][0], sc[rb][n][1]));
                    tm1 = fmaxf(tm1, fmaxf(sc[rb][n][2], sc[rb][n][3]));
                }
                tm0 = fmaxf(tm0, __shfl_xor_sync(0xffffffffu, tm0, 1));
                tm0 = fmaxf(tm0, __shfl_xor_sync(0xffffffffu, tm0, 2));
                tm1 = fmaxf(tm1, __shfl_xor_sync(0xffffffffu, tm1, 1));
                tm1 = fmaxf(tm1, __shfl_xor_sync(0xffffffffu, tm1, 2));

                float mn0 = fmaxf(m[rb][0], tm0), mn1 = fmaxf(m[rb][1], tm1);
                float f0 = fexp2(m[rb][0] - mn0);
                float f1 = fexp2(m[rb][1] - mn1);
                m[rb][0] = mn0; m[rb][1] = mn1;
                l[rb][0] *= f0; l[rb][1] *= f1;
                #pragma unroll
                for (int d = 0; d < 8; d++) {
                    oc[rb][d][0] *= f0; oc[rb][d][1] *= f0;
                    oc[rb][d][2] *= f1; oc[rb][d][3] *= f1;
                }
                #pragma unroll
                for (int n = 0; n < 8; n++) {
                    float p0 = fexp2(sc[rb][n][0] - mn0);
                    float p1 = fexp2(sc[rb][n][1] - mn0);
                    float p2 = fexp2(sc[rb][n][2] - mn1);
                    float p3 = fexp2(sc[rb][n][3] - mn1);
                    l[rb][0] += p0 + p1;
                    l[rb][1] += p2 + p3;
                    sc[rb][n][0] = __uint_as_float(f2tf(p0));
                    sc[rb][n][1] = __uint_as_float(f2tf(p1));
                    sc[rb][n][2] = __uint_as_float(f2tf(p2));
                    sc[rb][n][3] = __uint_as_float(f2tf(p3));
                }
            }

            // ---- O += P V : C-frag == A-frag under V row permutation ----
            #pragma unroll
            for (int kt = 0; kt < 8; kt++) {
                uint32_t pa0[4], pa1[4];
                pa0[0] = __float_as_uint(sc[0][kt][0]);
                pa0[1] = __float_as_uint(sc[0][kt][2]);
                pa0[2] = __float_as_uint(sc[0][kt][1]);
                pa0[3] = __float_as_uint(sc[0][kt][3]);
                pa1[0] = __float_as_uint(sc[1][kt][0]);
                pa1[1] = __float_as_uint(sc[1][kt][2]);
                pa1[2] = __float_as_uint(sc[1][kt][1]);
                pa1[3] = __float_as_uint(sc[1][kt][3]);

                const float* vb = vsb + (8 * kt + g) * KSV + qr;
                #pragma unroll
                for (int d = 0; d < 8; d++) {
                    uint32_t b0 = __float_as_uint(vb[8 * d]);
                    uint32_t b1 = __float_as_uint(vb[4 * KSV + 8 * d]);
                    mma_tf32(oc[0][d], pa0, b0, b1);
                    mma_tf32(oc[1][d], pa1, b0, b1);
                }
            }
        }
        __syncthreads();
    }

    // ---- finalize ----
    #pragma unroll
    for (int rb = 0; rb < 2; rb++) {
        float l0 = l[rb][0], l1 = l[rb][1];
        l0 += __shfl_xor_sync(0xffffffffu, l0, 1);
        l0 += __shfl_xor_sync(0xffffffffu, l0, 2);
        l1 += __shfl_xor_sync(0xffffffffu, l1, 1);
        l1 += __shfl_xor_sync(0xffffffffu, l1, 2);
        float inv0 = 1.0f / l0, inv1 = 1.0f / l1;

        float* o0 = o + base + (size_t)rg[rb][0] * DH;
        float* o1 = o + base + (size_t)rg[rb][1] * DH;
        #pragma unroll
        for (int d = 0; d < 8; d++) {
            float2 a, b;
            a.x = oc[rb][d][0] * inv0; a.y = oc[rb][d][1] * inv0;
            b.x = oc[rb][d][2] * inv1; b.y = oc[rb][d][3] * inv1;
            *(float2*)(o0 + 8 * d + 2 * g) = a;
            *(float2*)(o1 + 8 * d + 2 * g) = b;
        }
    }
}

extern "C" void kernel_launch(void* const* d_in, const int* in_sizes, int n_in,
                              void* d_out, int out_size)
{
    const float* q = (const float*)d_in[0];
    const float* k = (const float*)d_in[1];
    const float* v = (const float*)d_in[2];
    // d_in[3] (causal mask) applied analytically; not read.
    float* o = (float*)d_out;

    const int heads = in_sizes[0] / (S_LEN * DH);      // 64
    const int SMEM  = (2 * BN * KSK + 2 * BN * KSV) * (int)sizeof(float);  // 71680

    cudaFuncSetAttribute(fa_kernel, cudaFuncAttributeMaxDynamicSharedMemorySize, SMEM);

    dim3 grid(S_LEN / BM, heads);   // (16, 64)
    fa_kernel<<<grid, 128, SMEM>>>(q, k, v, o);
}